// round 1
// baseline (speedup 1.0000x reference)
#include <cuda_runtime.h>
#include <math.h>

// Problem constants
#define NBATCH 32
#define CCH    256
#define HH     56
#define WW     56
#define HWSZ   3136          // H*W
#define C5SZ   1280          // C*5

// Scratch (allocation-free rule: __device__ globals)
static __device__ __align__(16) float g_gelu[NBATCH * CCH * HWSZ];   // gelu(relu(x)), ~103 MB
static __device__ __align__(16) float g_a2[NBATCH * CCH * C5SZ];     // p6w * t2 / 56, ~42 MB

// ---------------------------------------------------------------------------
// Kernel 1: g = gelu(relu(x)), exact erf gelu. gelu(0)=0 so padding stays 0.
// ---------------------------------------------------------------------------
__global__ void k_gelu(const float4* __restrict__ x4) {
    const int total4 = NBATCH * CCH * HWSZ / 4;
    int i = blockIdx.x * blockDim.x + threadIdx.x;
    if (i >= total4) return;
    float4 v = x4[i];
    float4 r;
    r.x = (v.x > 0.f) ? 0.5f * v.x * (1.f + erff(v.x * 0.7071067811865476f)) : 0.f;
    r.y = (v.y > 0.f) ? 0.5f * v.y * (1.f + erff(v.y * 0.7071067811865476f)) : 0.f;
    r.z = (v.z > 0.f) ? 0.5f * v.z * (1.f + erff(v.z * 0.7071067811865476f)) : 0.f;
    r.w = (v.w > 0.f) ? 0.5f * v.w * (1.f + erff(v.w * 0.7071067811865476f)) : 0.f;
    ((float4*)g_gelu)[i] = r;
}

// ---------------------------------------------------------------------------
// Kernel 2 (GEMM1, NT): per batch n,
//   A'[c][m'] = p6w[c][m'] * (1/56) * sum_i x[c,i] * xshift[m'][i]
// where m' = c'*5+k, xshift row = x[c', i + 2k-4] masked on w-boundary.
// Block tile 128x128, BK=8, 256 threads, 8x8 microtile.
// Grid: (N/128=10, M/128=2, n=32)
// ---------------------------------------------------------------------------
__global__ __launch_bounds__(256, 2)
void k_gemm1(const float* __restrict__ x, const float* __restrict__ p6w) {
    const int n   = blockIdx.z;
    const int cm0 = blockIdx.y * 128;
    const int bn0 = blockIdx.x * 128;
    const float* __restrict__ Abase = x + (size_t)n * CCH * HWSZ;

    __shared__ __align__(16) float As[8][132];   // [k][m], padded
    __shared__ __align__(16) float Bs[8][132];   // [k][n'], padded

    const int tid  = threadIdx.x;
    const int tx   = tid & 15;
    const int ty   = tid >> 4;
    const int lrow = tid >> 1;          // 0..127: tile row this thread loads
    const int lk   = (tid & 1) * 4;     // 0 or 4: k-offset within BK

    const float* __restrict__ Arow = Abase + (size_t)(cm0 + lrow) * HWSZ;
    const int bm = bn0 + lrow;          // m' = c'*5 + k
    const int bc = bm / 5;
    const int bk = bm - bc * 5;
    const int bd = 2 * bk - 4;          // width shift: -4,-2,0,2,4
    const float* __restrict__ Brow = Abase + (size_t)bc * HWSZ;

    float acc[8][8];
#pragma unroll
    for (int i = 0; i < 8; i++)
#pragma unroll
        for (int j = 0; j < 8; j++) acc[i][j] = 0.f;

    float ra[4], rb[4];

    // prologue load (k0 = 0)
    {
        const float4 av = *(const float4*)(Arow + lk);
        ra[0] = av.x; ra[1] = av.y; ra[2] = av.z; ra[3] = av.w;
#pragma unroll
        for (int j = 0; j < 4; j++) {
            const int i  = lk + j;
            const int w  = i % WW;
            const int wp = w + bd;
            rb[j] = (wp >= 0 && wp < WW) ? Brow[i + bd] : 0.f;
        }
    }
#pragma unroll
    for (int j = 0; j < 4; j++) { As[lk + j][lrow] = ra[j]; Bs[lk + j][lrow] = rb[j]; }
    __syncthreads();

    const int iters = HWSZ / 8;   // 392
    for (int it = 0; it < iters; ++it) {
        // prefetch next tile into registers
        if (it + 1 < iters) {
            const int k0 = (it + 1) * 8;
            const float4 av = *(const float4*)(Arow + k0 + lk);
            ra[0] = av.x; ra[1] = av.y; ra[2] = av.z; ra[3] = av.w;
#pragma unroll
            for (int j = 0; j < 4; j++) {
                const int i  = k0 + lk + j;
                const int w  = i % WW;
                const int wp = w + bd;
                rb[j] = (wp >= 0 && wp < WW) ? Brow[i + bd] : 0.f;
            }
        }
        // compute on current smem tile
#pragma unroll
        for (int kk = 0; kk < 8; kk++) {
            const float4 a0 = *(const float4*)&As[kk][ty * 8];
            const float4 a1 = *(const float4*)&As[kk][ty * 8 + 4];
            const float4 b0 = *(const float4*)&Bs[kk][tx * 8];
            const float4 b1 = *(const float4*)&Bs[kk][tx * 8 + 4];
            float a[8] = {a0.x, a0.y, a0.z, a0.w, a1.x, a1.y, a1.z, a1.w};
            float b[8] = {b0.x, b0.y, b0.z, b0.w, b1.x, b1.y, b1.z, b1.w};
#pragma unroll
            for (int im = 0; im < 8; im++)
#pragma unroll
                for (int in = 0; in < 8; in++)
                    acc[im][in] += a[im] * b[in];
        }
        __syncthreads();
        if (it + 1 < iters) {
#pragma unroll
            for (int j = 0; j < 4; j++) { As[lk + j][lrow] = ra[j]; Bs[lk + j][lrow] = rb[j]; }
            __syncthreads();
        }
    }

    // epilogue: A' = p6w * t2, t2 = acc/56
    float* __restrict__ Dst = g_a2 + (size_t)n * CCH * C5SZ;
#pragma unroll
    for (int im = 0; im < 8; im++) {
        const int c = cm0 + ty * 8 + im;
        const float* __restrict__ pw = p6w + (size_t)c * C5SZ + bn0 + tx * 8;
        float*       __restrict__ dp = Dst + (size_t)c * C5SZ + bn0 + tx * 8;
#pragma unroll
        for (int in = 0; in < 8; in++)
            dp[in] = acc[im][in] * (1.0f / 56.0f) * pw[in];
    }
}

// ---------------------------------------------------------------------------
// Kernel 3 (GEMM2, NN): per batch n,
//   out[c][i] = (1/sqrt(1280)) * sum_{k'} A'[c][k'] * g[c'][i + (kk-2)*56]
// where k' = c'*5+kk; vertical shift = whole rows, validity = range check on i'.
// Block tile 128x128, BK=8. Grid: (ceil(3136/128)=25, 2, 32) — last i-tile predicated.
// ---------------------------------------------------------------------------
__global__ __launch_bounds__(256, 2)
void k_gemm2(float* __restrict__ out) {
    const int n   = blockIdx.z;
    const int cm0 = blockIdx.y * 128;
    const int i0  = blockIdx.x * 128;
    const float* __restrict__ Abase = g_a2   + (size_t)n * CCH * C5SZ;
    const float* __restrict__ G     = g_gelu + (size_t)n * CCH * HWSZ;

    __shared__ __align__(16) float As[8][132];   // [k'][c], padded (transposed store)
    __shared__ __align__(16) float Bs[8][128];   // [k'][i], natural

    const int tid  = threadIdx.x;
    const int tx   = tid & 15;
    const int ty   = tid >> 4;
    const int lrow = tid >> 1;
    const int lk   = (tid & 1) * 4;
    const float* __restrict__ Arow = Abase + (size_t)(cm0 + lrow) * C5SZ;

    const int brow = tid >> 5;          // 0..7 : k'-row within BK this thread loads
    const int bcol = (tid & 31) * 4;    // 0..124: i-col base (float4)

    float acc[8][8];
#pragma unroll
    for (int i = 0; i < 8; i++)
#pragma unroll
        for (int j = 0; j < 8; j++) acc[i][j] = 0.f;

    float ra[4];
    float4 rb4;

    // B-row loader: k' = k0+brow -> c' = k'/5, kk = k'%5, shift = (kk-2)*56.
    // Valid i interval is [lo,hi), both multiples of 4, so each float4 is all-or-nothing.
    auto i_this = i0 + bcol;

    // prologue (k0 = 0)
    {
        const float4 av = *(const float4*)(Arow + lk);
        ra[0] = av.x; ra[1] = av.y; ra[2] = av.z; ra[3] = av.w;
        const int kp    = brow;
        const int cpr   = kp / 5;
        const int kk5   = kp - cpr * 5;
        const int shift = (kk5 - 2) * WW;
        const int lo = (shift < 0) ? -shift : 0;
        const int hi = (shift > 0) ? (HWSZ - shift) : HWSZ;
        rb4 = (i_this >= lo && i_this < hi)
                ? *(const float4*)(G + (size_t)cpr * HWSZ + i_this + shift)
                : make_float4(0.f, 0.f, 0.f, 0.f);
    }
#pragma unroll
    for (int j = 0; j < 4; j++) As[lk + j][lrow] = ra[j];
    *(float4*)&Bs[brow][bcol] = rb4;
    __syncthreads();

    const int iters = C5SZ / 8;   // 160
    for (int it = 0; it < iters; ++it) {
        if (it + 1 < iters) {
            const int k0 = (it + 1) * 8;
            const float4 av = *(const float4*)(Arow + k0 + lk);
            ra[0] = av.x; ra[1] = av.y; ra[2] = av.z; ra[3] = av.w;
            const int kp    = k0 + brow;
            const int cpr   = kp / 5;
            const int kk5   = kp - cpr * 5;
            const int shift = (kk5 - 2) * WW;
            const int lo = (shift < 0) ? -shift : 0;
            const int hi = (shift > 0) ? (HWSZ - shift) : HWSZ;
            rb4 = (i_this >= lo && i_this < hi)
                    ? *(const float4*)(G + (size_t)cpr * HWSZ + i_this + shift)
                    : make_float4(0.f, 0.f, 0.f, 0.f);
        }
#pragma unroll
        for (int kk = 0; kk < 8; kk++) {
            const float4 a0 = *(const float4*)&As[kk][ty * 8];
            const float4 a1 = *(const float4*)&As[kk][ty * 8 + 4];
            const float4 b0 = *(const float4*)&Bs[kk][tx * 8];
            const float4 b1 = *(const float4*)&Bs[kk][tx * 8 + 4];
            float a[8] = {a0.x, a0.y, a0.z, a0.w, a1.x, a1.y, a1.z, a1.w};
            float b[8] = {b0.x, b0.y, b0.z, b0.w, b1.x, b1.y, b1.z, b1.w};
#pragma unroll
            for (int im = 0; im < 8; im++)
#pragma unroll
                for (int in = 0; in < 8; in++)
                    acc[im][in] += a[im] * b[in];
        }
        __syncthreads();
        if (it + 1 < iters) {
#pragma unroll
            for (int j = 0; j < 4; j++) As[lk + j][lrow] = ra[j];
            *(float4*)&Bs[brow][bcol] = rb4;
            __syncthreads();
        }
    }

    // epilogue: out = acc / sqrt(1280); predicate last i-tile
    const float scale = 0.027950849718747373f;  // 1/sqrt(1280)
    float* __restrict__ Obase = out + (size_t)n * CCH * HWSZ;
#pragma unroll
    for (int im = 0; im < 8; im++) {
        const int c = cm0 + ty * 8 + im;
        float* __restrict__ orow = Obase + (size_t)c * HWSZ;
#pragma unroll
        for (int in = 0; in < 8; in++) {
            const int i = i0 + tx * 8 + in;
            if (i < HWSZ) orow[i] = acc[im][in] * scale;
        }
    }
}

// ---------------------------------------------------------------------------
extern "C" void kernel_launch(void* const* d_in, const int* in_sizes, int n_in,
                              void* d_out, int out_size) {
    const float* x   = (const float*)d_in[0];   // [32,256,56,56] fp32
    const float* p6w = (const float*)d_in[1];   // [1,256,256,5] fp32
    float* out = (float*)d_out;                 // [32,256,56,56] fp32

    // 1) g = gelu(relu(x))
    const int total4 = NBATCH * CCH * HWSZ / 4;
    k_gelu<<<(total4 + 255) / 256, 256>>>((const float4*)x);

    // 2) A' = p6w * corr(x, xshift)/56   (t2 fused with gating)
    dim3 g1(C5SZ / 128, CCH / 128, NBATCH);   // (10, 2, 32)
    k_gemm1<<<g1, 256>>>(x, p6w);

    // 3) out = A' @ t5 / sqrt(1280)
    dim3 g2((HWSZ + 127) / 128, CCH / 128, NBATCH);   // (25, 2, 32)
    k_gemm2<<<g2, 256>>>(out);
}

// round 4
// speedup vs baseline: 1.7096x; 1.7096x over previous
#include <cuda_runtime.h>
#include <cuda_bf16.h>
#include <math.h>
#include <stdint.h>

// Problem constants
#define NBATCH 32
#define CCH    256
#define WW     56
#define HWSZ   3136          // H*W
#define C5SZ   1280          // C*5
#define KST    34            // smem K stride (bf16 elems): 32 + 2 pad -> 17-word rows

// Scratch (allocation-free rule: __device__ globals)
static __device__ __align__(16) float g_gelu[NBATCH * CCH * HWSZ];   // gelu(relu(x))
static __device__ __align__(16) float g_a2[NBATCH * CCH * C5SZ];     // p6w * t2 / 56

// ---------------------------------------------------------------------------
// mma.sync m16n8k16 bf16 (sm_80+ path; no sm_100a-only features)
// ---------------------------------------------------------------------------
__device__ __forceinline__ void mma16816(float d[4], const uint32_t a[4], const uint32_t b[2]) {
    asm volatile(
        "mma.sync.aligned.m16n8k16.row.col.f32.bf16.bf16.f32 "
        "{%0,%1,%2,%3}, {%4,%5,%6,%7}, {%8,%9}, {%0,%1,%2,%3};\n"
        : "+f"(d[0]), "+f"(d[1]), "+f"(d[2]), "+f"(d[3])
        : "r"(a[0]), "r"(a[1]), "r"(a[2]), "r"(a[3]), "r"(b[0]), "r"(b[1]));
}

// split a float pair into hi/lo bf16x2 words
__device__ __forceinline__ void split2(float x, float y, uint32_t& hi, uint32_t& lo) {
    __nv_bfloat162 h = __floats2bfloat162_rn(x, y);
    __nv_bfloat162 l = __floats2bfloat162_rn(x - __bfloat162float(h.x),
                                             y - __bfloat162float(h.y));
    hi = *reinterpret_cast<uint32_t*>(&h);
    lo = *reinterpret_cast<uint32_t*>(&l);
}

// ---------------------------------------------------------------------------
// Kernel 1: g = gelu(relu(x)) (exact erf form)
// ---------------------------------------------------------------------------
__global__ void k_gelu(const float4* __restrict__ x4) {
    const int total4 = NBATCH * CCH * HWSZ / 4;
    int i = blockIdx.x * blockDim.x + threadIdx.x;
    if (i >= total4) return;
    float4 v = x4[i];
    float4 r;
    r.x = (v.x > 0.f) ? 0.5f * v.x * (1.f + erff(v.x * 0.7071067811865476f)) : 0.f;
    r.y = (v.y > 0.f) ? 0.5f * v.y * (1.f + erff(v.y * 0.7071067811865476f)) : 0.f;
    r.z = (v.z > 0.f) ? 0.5f * v.z * (1.f + erff(v.z * 0.7071067811865476f)) : 0.f;
    r.w = (v.w > 0.f) ? 0.5f * v.w * (1.f + erff(v.w * 0.7071067811865476f)) : 0.f;
    ((float4*)g_gelu)[i] = r;
}

// ===========================================================================
// GEMM1 (warp-MMA, split-bf16):
//   A'[c][m'] = p6w[c][m'] * (1/56) * sum_i x[c,i] * x[c', i+2k-4] (masked)
// Block 128x128, BK=32 fp32-K, 98 chunks. Grid (10, 2, 32).
// ===========================================================================
__global__ __launch_bounds__(256, 1)
void k_gemm1_mma(const float* __restrict__ x, const float* __restrict__ p6w) {
    __shared__ __nv_bfloat16 Ah[128][KST], Al[128][KST], Bh[128][KST], Bl[128][KST];

    const int tid  = threadIdx.x;
    const int lane = tid & 31;
    const int wid  = tid >> 5;
    const int g    = lane >> 2;
    const int t4   = lane & 3;
    const int wm   = wid & 1;       // 0..1  (64-row M slab)
    const int wn   = wid >> 1;      // 0..3  (32-col N slab)

    const int n   = blockIdx.z;
    const int cm0 = blockIdx.y * 128;
    const int bn0 = blockIdx.x * 128;
    const float* __restrict__ X = x + (size_t)n * CCH * HWSZ;

    // loader: 2 threads per row, 16 floats each
    const int lr = tid >> 1;
    const int kq = (tid & 1) * 16;
    const float* __restrict__ Arow = X + (size_t)(cm0 + lr) * HWSZ;
    const int bm = bn0 + lr;
    const int bc = bm / 5;
    const int bd = 2 * (bm - 5 * bc) - 4;           // -4,-2,0,2,4
    const float* __restrict__ Brow = X + (size_t)bc * HWSZ;

    float ra[16], rb[16];

    auto loadChunk = [&](int k0) {
#pragma unroll
        for (int q = 0; q < 4; ++q) {
            const float4 v = *(const float4*)(Arow + k0 + kq + q * 4);
            ra[q * 4 + 0] = v.x; ra[q * 4 + 1] = v.y;
            ra[q * 4 + 2] = v.z; ra[q * 4 + 3] = v.w;
        }
        const int ig0 = k0 + kq;
        const int w0  = ig0 % WW;
#pragma unroll
        for (int j = 0; j < 16; ++j) {
            int w = w0 + j; if (w >= WW) w -= WW;
            const int wp = w + bd;
            rb[j] = (wp >= 0 && wp < WW) ? __ldg(Brow + ig0 + j + bd) : 0.f;
        }
    };
    auto storeChunk = [&]() {
#pragma unroll
        for (int j = 0; j < 16; j += 2) {
            uint32_t hi, lo;
            split2(ra[j], ra[j + 1], hi, lo);
            *(uint32_t*)&Ah[lr][kq + j] = hi;
            *(uint32_t*)&Al[lr][kq + j] = lo;
            split2(rb[j], rb[j + 1], hi, lo);
            *(uint32_t*)&Bh[lr][kq + j] = hi;
            *(uint32_t*)&Bl[lr][kq + j] = lo;
        }
    };

    float acc[4][4][4];
#pragma unroll
    for (int a = 0; a < 4; a++)
#pragma unroll
        for (int b = 0; b < 4; b++)
#pragma unroll
            for (int c = 0; c < 4; c++) acc[a][b][c] = 0.f;

    loadChunk(0);
    storeChunk();
    __syncthreads();

    const int NCH = HWSZ / 32;   // 98
    for (int tch = 0; tch < NCH; ++tch) {
        if (tch + 1 < NCH) loadChunk((tch + 1) * 32);

#pragma unroll
        for (int ks = 0; ks < 32; ks += 16) {
            uint32_t ah[4][4], al[4][4], bh[4][2], bl[4][2];
            const int kb = ks + t4 * 2;
#pragma unroll
            for (int mt = 0; mt < 4; ++mt) {
                const int r0 = wm * 64 + mt * 16 + g;
                ah[mt][0] = *(const uint32_t*)&Ah[r0][kb];
                ah[mt][1] = *(const uint32_t*)&Ah[r0 + 8][kb];
                ah[mt][2] = *(const uint32_t*)&Ah[r0][kb + 8];
                ah[mt][3] = *(const uint32_t*)&Ah[r0 + 8][kb + 8];
                al[mt][0] = *(const uint32_t*)&Al[r0][kb];
                al[mt][1] = *(const uint32_t*)&Al[r0 + 8][kb];
                al[mt][2] = *(const uint32_t*)&Al[r0][kb + 8];
                al[mt][3] = *(const uint32_t*)&Al[r0 + 8][kb + 8];
            }
#pragma unroll
            for (int nt = 0; nt < 4; ++nt) {
                const int rn = wn * 32 + nt * 8 + g;
                bh[nt][0] = *(const uint32_t*)&Bh[rn][kb];
                bh[nt][1] = *(const uint32_t*)&Bh[rn][kb + 8];
                bl[nt][0] = *(const uint32_t*)&Bl[rn][kb];
                bl[nt][1] = *(const uint32_t*)&Bl[rn][kb + 8];
            }
#pragma unroll
            for (int mt = 0; mt < 4; ++mt)
#pragma unroll
                for (int nt = 0; nt < 4; ++nt) mma16816(acc[mt][nt], ah[mt], bh[nt]);
#pragma unroll
            for (int mt = 0; mt < 4; ++mt)
#pragma unroll
                for (int nt = 0; nt < 4; ++nt) mma16816(acc[mt][nt], ah[mt], bl[nt]);
#pragma unroll
            for (int mt = 0; mt < 4; ++mt)
#pragma unroll
                for (int nt = 0; nt < 4; ++nt) mma16816(acc[mt][nt], al[mt], bh[nt]);
        }
        __syncthreads();
        if (tch + 1 < NCH) {
            storeChunk();
            __syncthreads();
        }
    }

    // epilogue: A' = acc * (1/56) * p6w  -> g_a2
    float* __restrict__ Dst = g_a2 + (size_t)n * CCH * C5SZ;
#pragma unroll
    for (int mt = 0; mt < 4; ++mt) {
        const int c0 = cm0 + wm * 64 + mt * 16 + g;
#pragma unroll
        for (int nt = 0; nt < 4; ++nt) {
            const int col = bn0 + wn * 32 + nt * 8 + t4 * 2;
            const float2 w0 = __ldg((const float2*)(p6w + (size_t)c0 * C5SZ + col));
            const float2 w1 = __ldg((const float2*)(p6w + (size_t)(c0 + 8) * C5SZ + col));
            float2 o0, o1;
            o0.x = acc[mt][nt][0] * (1.0f / 56.0f) * w0.x;
            o0.y = acc[mt][nt][1] * (1.0f / 56.0f) * w0.y;
            o1.x = acc[mt][nt][2] * (1.0f / 56.0f) * w1.x;
            o1.y = acc[mt][nt][3] * (1.0f / 56.0f) * w1.y;
            *(float2*)(Dst + (size_t)c0 * C5SZ + col)       = o0;
            *(float2*)(Dst + (size_t)(c0 + 8) * C5SZ + col) = o1;
        }
    }
}

// ===========================================================================
// GEMM2 (warp-MMA, split-bf16):
//   out[c][i] = (1/sqrt(1280)) * sum_{k'} A'[c][k'] * G[c'][i + (kk-2)*56]
// Block 128(M=c) x 128(N=i), BK=32 over k'=1280 (40 chunks). Grid (25, 2, 32).
// B loader transposes G tile into smem [i][k'].
// ===========================================================================
__global__ __launch_bounds__(256, 1)
void k_gemm2_mma(float* __restrict__ out) {
    __shared__ __nv_bfloat16 Ah[128][KST], Al[128][KST], Bh[128][KST], Bl[128][KST];

    const int tid  = threadIdx.x;
    const int lane = tid & 31;
    const int wid  = tid >> 5;
    const int g    = lane >> 2;
    const int t4   = lane & 3;
    const int wm   = wid & 1;
    const int wn   = wid >> 1;

    const int n   = blockIdx.z;
    const int cm0 = blockIdx.y * 128;
    const int i0  = blockIdx.x * 128;
    const float* __restrict__ Abase = g_a2   + (size_t)n * CCH * C5SZ;
    const float* __restrict__ G     = g_gelu + (size_t)n * CCH * HWSZ;

    // A loader: 2 threads per row, 16 floats each
    const int lr = tid >> 1;
    const int kq = (tid & 1) * 16;
    const float* __restrict__ Arow = Abase + (size_t)(cm0 + lr) * C5SZ;

    // B loader: warp w covers k'-local rows {w, w+8, w+16, w+24}; lane -> 4 i's
    const int il = lane * 4;            // i-local base 0..124
    const int ig = i0 + il;             // global output i of first elem

    float  ra[16];
    float4 rbv[4];

    auto loadChunk = [&](int k0) {
#pragma unroll
        for (int q = 0; q < 4; ++q) {
            const float4 v = *(const float4*)(Arow + k0 + kq + q * 4);
            ra[q * 4 + 0] = v.x; ra[q * 4 + 1] = v.y;
            ra[q * 4 + 2] = v.z; ra[q * 4 + 3] = v.w;
        }
#pragma unroll
        for (int p = 0; p < 4; ++p) {
            const int kp    = k0 + wid + p * 8;        // global k'
            const int cpr   = kp / 5;
            const int kk5   = kp - cpr * 5;
            const int shift = (kk5 - 2) * WW;
            const int lo = (shift < 0) ? -shift : 0;
            const int hi = (shift > 0) ? (HWSZ - shift) : HWSZ;
            rbv[p] = (ig >= lo && ig < hi)
                       ? *(const float4*)(G + (size_t)cpr * HWSZ + ig + shift)
                       : make_float4(0.f, 0.f, 0.f, 0.f);
        }
    };
    auto storeChunk = [&]() {
#pragma unroll
        for (int j = 0; j < 16; j += 2) {
            uint32_t hi, lo;
            split2(ra[j], ra[j + 1], hi, lo);
            *(uint32_t*)&Ah[lr][kq + j] = hi;
            *(uint32_t*)&Al[lr][kq + j] = lo;
        }
#pragma unroll
        for (int p = 0; p < 4; ++p) {
            const int kl = wid + p * 8;
            const float e[4] = {rbv[p].x, rbv[p].y, rbv[p].z, rbv[p].w};
#pragma unroll
            for (int jj = 0; jj < 4; ++jj) {
                const __nv_bfloat16 h = __float2bfloat16(e[jj]);
                const __nv_bfloat16 l = __float2bfloat16(e[jj] - __bfloat162float(h));
                Bh[il + jj][kl] = h;
                Bl[il + jj][kl] = l;
            }
        }
    };

    float acc[4][4][4];
#pragma unroll
    for (int a = 0; a < 4; a++)
#pragma unroll
        for (int b = 0; b < 4; b++)
#pragma unroll
            for (int c = 0; c < 4; c++) acc[a][b][c] = 0.f;

    loadChunk(0);
    storeChunk();
    __syncthreads();

    const int NCH = C5SZ / 32;   // 40
    for (int tch = 0; tch < NCH; ++tch) {
        if (tch + 1 < NCH) loadChunk((tch + 1) * 32);

#pragma unroll
        for (int ks = 0; ks < 32; ks += 16) {
            uint32_t ah[4][4], al[4][4], bh[4][2], bl[4][2];
            const int kb = ks + t4 * 2;
#pragma unroll
            for (int mt = 0; mt < 4; ++mt) {
                const int r0 = wm * 64 + mt * 16 + g;
                ah[mt][0] = *(const uint32_t*)&Ah[r0][kb];
                ah[mt][1] = *(const uint32_t*)&Ah[r0 + 8][kb];
                ah[mt][2] = *(const uint32_t*)&Ah[r0][kb + 8];
                ah[mt][3] = *(const uint32_t*)&Ah[r0 + 8][kb + 8];
                al[mt][0] = *(const uint32_t*)&Al[r0][kb];
                al[mt][1] = *(const uint32_t*)&Al[r0 + 8][kb];
                al[mt][2] = *(const uint32_t*)&Al[r0][kb + 8];
                al[mt][3] = *(const uint32_t*)&Al[r0 + 8][kb + 8];
            }
#pragma unroll
            for (int nt = 0; nt < 4; ++nt) {
                const int rn = wn * 32 + nt * 8 + g;
                bh[nt][0] = *(const uint32_t*)&Bh[rn][kb];
                bh[nt][1] = *(const uint32_t*)&Bh[rn][kb + 8];
                bl[nt][0] = *(const uint32_t*)&Bl[rn][kb];
                bl[nt][1] = *(const uint32_t*)&Bl[rn][kb + 8];
            }
#pragma unroll
            for (int mt = 0; mt < 4; ++mt)
#pragma unroll
                for (int nt = 0; nt < 4; ++nt) mma16816(acc[mt][nt], ah[mt], bh[nt]);
#pragma unroll
            for (int mt = 0; mt < 4; ++mt)
#pragma unroll
                for (int nt = 0; nt < 4; ++nt) mma16816(acc[mt][nt], ah[mt], bl[nt]);
#pragma unroll
            for (int mt = 0; mt < 4; ++mt)
#pragma unroll
                for (int nt = 0; nt < 4; ++nt) mma16816(acc[mt][nt], al[mt], bh[nt]);
        }
        __syncthreads();
        if (tch + 1 < NCH) {
            storeChunk();
            __syncthreads();
        }
    }

    // epilogue: out = acc / sqrt(1280); guard i < 3136
    const float scale = 0.027950849718747373f;
    float* __restrict__ Obase = out + (size_t)n * CCH * HWSZ;
#pragma unroll
    for (int mt = 0; mt < 4; ++mt) {
        const int c0 = cm0 + wm * 64 + mt * 16 + g;
#pragma unroll
        for (int nt = 0; nt < 4; ++nt) {
            const int i = i0 + wn * 32 + nt * 8 + t4 * 2;
            if (i < HWSZ) {
                float2 o0, o1;
                o0.x = acc[mt][nt][0] * scale;
                o0.y = acc[mt][nt][1] * scale;
                o1.x = acc[mt][nt][2] * scale;
                o1.y = acc[mt][nt][3] * scale;
                *(float2*)(Obase + (size_t)c0 * HWSZ + i)       = o0;
                *(float2*)(Obase + (size_t)(c0 + 8) * HWSZ + i) = o1;
            }
        }
    }
}

// ---------------------------------------------------------------------------
extern "C" void kernel_launch(void* const* d_in, const int* in_sizes, int n_in,
                              void* d_out, int out_size) {
    const float* x   = (const float*)d_in[0];   // [32,256,56,56] fp32
    const float* p6w = (const float*)d_in[1];   // [1,256,256,5] fp32
    float* out = (float*)d_out;                 // [32,256,56,56] fp32

    const int total4 = NBATCH * CCH * HWSZ / 4;
    k_gelu<<<(total4 + 255) / 256, 256>>>((const float4*)x);

    dim3 g1(C5SZ / 128, CCH / 128, NBATCH);          // (10, 2, 32)
    k_gemm1_mma<<<g1, 256>>>(x, p6w);

    dim3 g2((HWSZ + 127) / 128, CCH / 128, NBATCH);  // (25, 2, 32)
    k_gemm2_mma<<<g2, 256>>>(out);
}